// round 6
// baseline (speedup 1.0000x reference)
#include <cuda_runtime.h>
#include <cstdint>
#include <cfloat>

#define BB 16
#define CH 32
#define HH 256
#define WW 256
#define NCODES 256
#define NSTEPS 5
#define HW (HH*WW)
#define NPIX (BB*HW)

__device__ float g_state[(size_t)NPIX * CH];
__device__ float g_h[(size_t)NPIX * CH];

// ---------- packed f32x2 helpers ----------
__device__ __forceinline__ unsigned long long pack2(float a, float b) {
    unsigned long long r;
    asm("mov.b64 %0,{%1,%2};" : "=l"(r) : "f"(a), "f"(b));
    return r;
}
__device__ __forceinline__ void unpack2(float& a, float& b, unsigned long long v) {
    asm("mov.b64 {%0,%1},%2;" : "=f"(a), "=f"(b) : "l"(v));
}
__device__ __forceinline__ void ffma2(unsigned long long& d, unsigned long long a, unsigned long long b) {
    asm("fma.rn.f32x2 %0,%1,%2,%0;" : "+l"(d) : "l"(a), "l"(b));
}
__device__ __forceinline__ float sigf(float x) { return 1.0f / (1.0f + __expf(-x)); }

__device__ __forceinline__ float to_tf32(float x) {
    float r;
    asm("cvt.rna.tf32.f32 %0, %1;" : "=f"(r) : "f"(x));
    return r;
}
__device__ __forceinline__ void mma_tf32(float& d0, float& d1, float& d2, float& d3,
                                         uint32_t a0, uint32_t a1, uint32_t a2, uint32_t a3,
                                         uint32_t b0, uint32_t b1) {
    asm volatile(
        "mma.sync.aligned.m16n8k8.row.col.f32.tf32.tf32.f32 "
        "{%0,%1,%2,%3}, {%4,%5,%6,%7}, {%8,%9}, {%0,%1,%2,%3};"
        : "+f"(d0), "+f"(d1), "+f"(d2), "+f"(d3)
        : "r"(a0), "r"(a1), "r"(a2), "r"(a3), "r"(b0), "r"(b1));
}

// ---------- stem: conv3x3 1->32 + relu ----------
__global__ __launch_bounds__(256) void stem_kernel(
    const float* __restrict__ x, const float* __restrict__ w, const float* __restrict__ b)
{
    __shared__ float ws[CH * 9];
    __shared__ float bs[CH];
    for (int i = threadIdx.x; i < CH * 9; i += 256) ws[i] = w[i];
    if (threadIdx.x < CH) bs[threadIdx.x] = b[threadIdx.x];
    __syncthreads();

    int pid = blockIdx.x * 256 + threadIdx.x;
    int xx = pid & (WW - 1);
    int yy = (pid >> 8) & (HH - 1);

    float in9[9];
#pragma unroll
    for (int ky = 0; ky < 3; ky++)
#pragma unroll
        for (int kx = 0; kx < 3; kx++) {
            int iy = yy + ky - 1, ix = xx + kx - 1;
            float v = 0.0f;
            if ((unsigned)iy < (unsigned)HH && (unsigned)ix < (unsigned)WW)
                v = __ldg(x + pid + (ky - 1) * WW + (kx - 1));
            in9[ky * 3 + kx] = v;
        }
    float acc[CH];
#pragma unroll
    for (int c = 0; c < CH; c++) acc[c] = bs[c];
#pragma unroll
    for (int t = 0; t < 9; t++) {
        float v = in9[t];
#pragma unroll
        for (int c = 0; c < CH; c++) acc[c] += v * ws[c * 9 + t];
    }
    float4* op = (float4*)(g_state + (size_t)pid * CH);
#pragma unroll
    for (int q = 0; q < 8; q++) {
        float4 o;
        o.x = fmaxf(acc[q * 4 + 0], 0.f);
        o.y = fmaxf(acc[q * 4 + 1], 0.f);
        o.z = fmaxf(acc[q * 4 + 2], 0.f);
        o.w = fmaxf(acc[q * 4 + 3], 0.f);
        op[q] = o;
    }
}

// ---------- conv3x3 32->32 + relu : g_state -> g_h ----------
__global__ __launch_bounds__(128) void conv3_relu_kernel(
    const float* __restrict__ w, const float* __restrict__ bias)
{
    __shared__ __align__(16) float ws[9 * CH * CH];  // [tap][ic][oc]
    __shared__ float bs[CH];
    int tid = threadIdx.x;
    for (int i = tid; i < 9 * CH * CH; i += 128) {
        int oc = i & 31, ic = (i >> 5) & 31, tap = i >> 10;
        ws[i] = w[(oc * CH + ic) * 9 + tap];
    }
    if (tid < CH) bs[tid] = bias[tid];
    __syncthreads();

    int quarter = tid & 3;
    int og = tid >> 2;
    int pix0 = (blockIdx.x * 32 + og) * 8;
    int x0 = pix0 & (WW - 1);
    int yy = (pix0 >> 8) & (HH - 1);
    int oc0 = quarter * 8;

    unsigned long long acc[8][4];
#pragma unroll
    for (int p = 0; p < 8; p++)
#pragma unroll
        for (int m = 0; m < 4; m++)
            acc[p][m] = pack2(bs[oc0 + 2 * m], bs[oc0 + 2 * m + 1]);

#pragma unroll
    for (int ky = 0; ky < 3; ky++) {
        int iy = yy + ky - 1;
        if ((unsigned)iy >= (unsigned)HH) continue;
        const float* rowbase = g_state + ((size_t)pix0 + (ky - 1) * WW) * CH;
#pragma unroll 1
        for (int ic4 = 0; ic4 < 8; ic4++) {
            float4 in10[10];
#pragma unroll
            for (int p = 0; p < 10; p++) {
                int ix = x0 + p - 1;
                float4 v = make_float4(0.f, 0.f, 0.f, 0.f);
                if ((unsigned)ix < (unsigned)WW)
                    v = __ldg((const float4*)(rowbase + (p - 1) * CH) + ic4);
                in10[p] = v;
            }
#pragma unroll
            for (int kx = 0; kx < 3; kx++) {
                const float* wrow = ws + (ky * 3 + kx) * (CH * CH) + oc0;
#pragma unroll
                for (int j = 0; j < 4; j++) {
                    int ic = ic4 * 4 + j;
                    const ulonglong2* wp = (const ulonglong2*)(wrow + ic * CH);
                    ulonglong2 wa = wp[0];
                    ulonglong2 wb = wp[1];
#pragma unroll
                    for (int p = 0; p < 8; p++) {
                        float v;
                        if (j == 0) v = in10[p + kx].x;
                        else if (j == 1) v = in10[p + kx].y;
                        else if (j == 2) v = in10[p + kx].z;
                        else v = in10[p + kx].w;
                        unsigned long long vp = pack2(v, v);
                        ffma2(acc[p][0], vp, wa.x);
                        ffma2(acc[p][1], vp, wa.y);
                        ffma2(acc[p][2], vp, wb.x);
                        ffma2(acc[p][3], vp, wb.y);
                    }
                }
            }
        }
    }
#pragma unroll
    for (int p = 0; p < 8; p++) {
        float4* op = (float4*)(g_h + ((size_t)pix0 + p) * CH + oc0);
#pragma unroll
        for (int q = 0; q < 2; q++) {
            float a, b;
            unpack2(a, b, acc[p][2 * q]);
            float c, d;
            unpack2(c, d, acc[p][2 * q + 1]);
            float4 o;
            o.x = fmaxf(a, 0.f); o.y = fmaxf(b, 0.f);
            o.z = fmaxf(c, 0.f); o.w = fmaxf(d, 0.f);
            op[q] = o;
        }
    }
}

// ---------- fused blend + VQ, all tensor-core (split-tf32 3-pass) ----------
// 128 threads = 4 warps = 128 pixels/CTA; warp handles 32 rows.
// Phase 1: delta = H@W2^T + b2, t = S@Wt^T + bt  (MMA), z = d + sig(t)*(s-d)
//          in accumulator fragments; shuffle-transpose to A-fragment layout.
// Phase 2: scores = z @ cb^T (MMA), argmin(0.5||c||^2 - score) -> code -> g_state.
#define WSTR 40    // weight smem stride: (8s+kq)*40+n -> conflict-free
#define BSTRIDE 264

__global__ __launch_bounds__(128) void fused_blend_vq_kernel(
    const float* __restrict__ w2g, const float* __restrict__ b2g,
    const float* __restrict__ wtg, const float* __restrict__ btg,
    const float* __restrict__ cb)
{
    __shared__ float sW2[CH * WSTR];   // [ic][oc]
    __shared__ float sWt[CH * WSTR];
    __shared__ float sBv[CH * BSTRIDE]; // [ch][code] fp32
    __shared__ float cn[NCODES];
    __shared__ float b2s[CH], bts[CH];

    int tid = threadIdx.x;
    for (int i = tid; i < CH * CH; i += 128) {
        int oc = i & 31, ic = i >> 5;
        sW2[ic * WSTR + oc] = w2g[oc * CH + ic];
        sWt[ic * WSTR + oc] = wtg[oc * CH + ic];
    }
    for (int i = tid; i < NCODES * CH; i += 128) {
        int code = i >> 5, c = i & 31;
        sBv[c * BSTRIDE + code] = __ldg(cb + i);
    }
#pragma unroll
    for (int r = 0; r < 2; r++) {
        int k = tid + r * 128;
        float s = 0.0f;
        const float* cr = cb + k * CH;
#pragma unroll
        for (int c = 0; c < CH; c++) { float v = __ldg(cr + c); s += v * v; }
        cn[k] = 0.5f * s;
    }
    if (tid < CH) { b2s[tid] = b2g[tid]; bts[tid] = btg[tid]; }
    __syncthreads();

    int wid = tid >> 5, lid = tid & 31;
    int kq = lid & 3;
    int nb = lid >> 2;
    int rbase = blockIdx.x * 128 + wid * 32 + nb;   // this lane's base row

    uint32_t ah[4][8], al[4][8];   // z A-fragments (filled per m-tile)

#pragma unroll
    for (int mt = 0; mt < 2; mt++) {
        // --- load S,H A-fragments for rows rbase+16mt (+0 and +8) ---
        uint32_t shh[2][8], shl[2][8], hhh[2][8], hhl[2][8];
#pragma unroll
        for (int slot = 0; slot < 2; slot++) {
            size_t row = (size_t)(rbase + 16 * mt + 8 * slot);
            const float* sp = g_state + row * CH + kq;
            const float* hp = g_h + row * CH + kq;
#pragma unroll
            for (int t = 0; t < 8; t++) {
                float sv = __ldg(sp + 4 * t);
                float sh = to_tf32(sv);
                shh[slot][t] = __float_as_uint(sh);
                shl[slot][t] = __float_as_uint(to_tf32(sv - sh));
                float hv = __ldg(hp + 4 * t);
                float hh = to_tf32(hv);
                hhh[slot][t] = __float_as_uint(hh);
                hhl[slot][t] = __float_as_uint(to_tf32(hv - hh));
            }
        }

        float z0[4][2], z1[4][2];   // [nt][parity]: rows rbase+16mt, +8
#pragma unroll
        for (int nt = 0; nt < 4; nt++) {
            float dh0 = 0.f, dh1 = 0.f, dh2 = 0.f, dh3 = 0.f;
            float dc0 = 0.f, dc1 = 0.f, dc2 = 0.f, dc3 = 0.f;
            float th0 = 0.f, th1 = 0.f, th2 = 0.f, th3 = 0.f;
            float tc0 = 0.f, tc1 = 0.f, tc2 = 0.f, tc3 = 0.f;
#pragma unroll
            for (int s = 0; s < 4; s++) {
                int ncol = nt * 8 + nb;
                float w0 = sW2[(8 * s + kq) * WSTR + ncol];
                float w1 = sW2[(8 * s + kq + 4) * WSTR + ncol];
                float wh0f = to_tf32(w0), wh1f = to_tf32(w1);
                uint32_t wh0 = __float_as_uint(wh0f);
                uint32_t wh1 = __float_as_uint(wh1f);
                uint32_t wl0 = __float_as_uint(to_tf32(w0 - wh0f));
                uint32_t wl1 = __float_as_uint(to_tf32(w1 - wh1f));
                mma_tf32(dh0, dh1, dh2, dh3, hhh[0][2*s], hhh[1][2*s], hhh[0][2*s+1], hhh[1][2*s+1], wh0, wh1);
                mma_tf32(dc0, dc1, dc2, dc3, hhl[0][2*s], hhl[1][2*s], hhl[0][2*s+1], hhl[1][2*s+1], wh0, wh1);
                mma_tf32(dc0, dc1, dc2, dc3, hhh[0][2*s], hhh[1][2*s], hhh[0][2*s+1], hhh[1][2*s+1], wl0, wl1);

                float u0 = sWt[(8 * s + kq) * WSTR + ncol];
                float u1 = sWt[(8 * s + kq + 4) * WSTR + ncol];
                float uh0f = to_tf32(u0), uh1f = to_tf32(u1);
                uint32_t uh0 = __float_as_uint(uh0f);
                uint32_t uh1 = __float_as_uint(uh1f);
                uint32_t ul0 = __float_as_uint(to_tf32(u0 - uh0f));
                uint32_t ul1 = __float_as_uint(to_tf32(u1 - uh1f));
                mma_tf32(th0, th1, th2, th3, shh[0][2*s], shh[1][2*s], shh[0][2*s+1], shh[1][2*s+1], uh0, uh1);
                mma_tf32(tc0, tc1, tc2, tc3, shl[0][2*s], shl[1][2*s], shl[0][2*s+1], shl[1][2*s+1], uh0, uh1);
                mma_tf32(tc0, tc1, tc2, tc3, shh[0][2*s], shh[1][2*s], shh[0][2*s+1], shh[1][2*s+1], ul0, ul1);
            }
            int c0 = nt * 8 + 2 * kq;
            float d0 = dh0 + dc0 + b2s[c0],     d1 = dh1 + dc1 + b2s[c0 + 1];
            float d2 = dh2 + dc2 + b2s[c0],     d3 = dh3 + dc3 + b2s[c0 + 1];
            float t0 = th0 + tc0 + bts[c0],     t1 = th1 + tc1 + bts[c0 + 1];
            float t2 = th2 + tc2 + bts[c0],     t3 = th3 + tc3 + bts[c0 + 1];
            size_t r = (size_t)(rbase + 16 * mt);
            float2 sa = *(const float2*)(g_state + r * CH + c0);
            float2 sb = *(const float2*)(g_state + (r + 8) * CH + c0);
            z0[nt][0] = d0 + sigf(t0) * (sa.x - d0);
            z0[nt][1] = d1 + sigf(t1) * (sa.y - d1);
            z1[nt][0] = d2 + sigf(t2) * (sb.x - d2);
            z1[nt][1] = d3 + sigf(t3) * (sb.y - d3);
        }

        // --- shuffle-transpose: accumulator layout -> A-fragment layout ---
        int grp = lid & 0x1C;
#pragma unroll
        for (int t = 0; t < 8; t++) {
            int nt = t >> 1;
            int h = (t & 1) ? (2 + (kq >> 1)) : (kq >> 1);
            int src = grp | h;
            float v0 = __shfl_sync(0xffffffffu, z0[nt][0], src);
            float v1 = __shfl_sync(0xffffffffu, z0[nt][1], src);
            float zk = (kq & 1) ? v1 : v0;
            float zh = to_tf32(zk);
            ah[2 * mt][t] = __float_as_uint(zh);
            al[2 * mt][t] = __float_as_uint(to_tf32(zk - zh));
            v0 = __shfl_sync(0xffffffffu, z1[nt][0], src);
            v1 = __shfl_sync(0xffffffffu, z1[nt][1], src);
            zk = (kq & 1) ? v1 : v0;
            zh = to_tf32(zk);
            ah[2 * mt + 1][t] = __float_as_uint(zh);
            al[2 * mt + 1][t] = __float_as_uint(to_tf32(zk - zh));
        }
    }

    // ---------- VQ phase ----------
    float best[4] = {FLT_MAX, FLT_MAX, FLT_MAX, FLT_MAX};
    int bi[4] = {0, 0, 0, 0};

#pragma unroll 1
    for (int chunk = 0; chunk < 8; chunk++) {
#pragma unroll
        for (int nt = 0; nt < 4; nt++) {
            int col = chunk * 32 + nt * 8 + nb;
            float dAh0 = 0.f, dAh1 = 0.f, dAh2 = 0.f, dAh3 = 0.f;
            float dAc0 = 0.f, dAc1 = 0.f, dAc2 = 0.f, dAc3 = 0.f;
            float dBh0 = 0.f, dBh1 = 0.f, dBh2 = 0.f, dBh3 = 0.f;
            float dBc0 = 0.f, dBc1 = 0.f, dBc2 = 0.f, dBc3 = 0.f;
#pragma unroll
            for (int s = 0; s < 4; s++) {
                float v0 = sBv[(8 * s + kq) * BSTRIDE + col];
                float v1 = sBv[(8 * s + 4 + kq) * BSTRIDE + col];
                float h0 = to_tf32(v0), h1 = to_tf32(v1);
                uint32_t bh0 = __float_as_uint(h0);
                uint32_t bh1 = __float_as_uint(h1);
                uint32_t bl0 = __float_as_uint(to_tf32(v0 - h0));
                uint32_t bl1 = __float_as_uint(to_tf32(v1 - h1));
                mma_tf32(dAh0, dAh1, dAh2, dAh3, ah[0][2*s], ah[1][2*s], ah[0][2*s+1], ah[1][2*s+1], bh0, bh1);
                mma_tf32(dAc0, dAc1, dAc2, dAc3, al[0][2*s], al[1][2*s], al[0][2*s+1], al[1][2*s+1], bh0, bh1);
                mma_tf32(dAc0, dAc1, dAc2, dAc3, ah[0][2*s], ah[1][2*s], ah[0][2*s+1], ah[1][2*s+1], bl0, bl1);
                mma_tf32(dBh0, dBh1, dBh2, dBh3, ah[2][2*s], ah[3][2*s], ah[2][2*s+1], ah[3][2*s+1], bh0, bh1);
                mma_tf32(dBc0, dBc1, dBc2, dBc3, al[2][2*s], al[3][2*s], al[2][2*s+1], al[3][2*s+1], bh0, bh1);
                mma_tf32(dBc0, dBc1, dBc2, dBc3, ah[2][2*s], ah[3][2*s], ah[2][2*s+1], ah[3][2*s+1], bl0, bl1);
            }
            int c0 = chunk * 32 + nt * 8 + 2 * kq;
            float cna = cn[c0], cnb = cn[c0 + 1];
            float m;
            m = cna - (dAh0 + dAc0); if (m < best[0]) { best[0] = m; bi[0] = c0; }
            m = cnb - (dAh1 + dAc1); if (m < best[0]) { best[0] = m; bi[0] = c0 + 1; }
            m = cna - (dAh2 + dAc2); if (m < best[1]) { best[1] = m; bi[1] = c0; }
            m = cnb - (dAh3 + dAc3); if (m < best[1]) { best[1] = m; bi[1] = c0 + 1; }
            m = cna - (dBh0 + dBc0); if (m < best[2]) { best[2] = m; bi[2] = c0; }
            m = cnb - (dBh1 + dBc1); if (m < best[2]) { best[2] = m; bi[2] = c0 + 1; }
            m = cna - (dBh2 + dBc2); if (m < best[3]) { best[3] = m; bi[3] = c0; }
            m = cnb - (dBh3 + dBc3); if (m < best[3]) { best[3] = m; bi[3] = c0 + 1; }
        }
    }

#pragma unroll
    for (int off = 1; off <= 2; off <<= 1) {
#pragma unroll
        for (int rr = 0; rr < 4; rr++) {
            float ob = __shfl_xor_sync(0xffffffffu, best[rr], off);
            int oi = __shfl_xor_sync(0xffffffffu, bi[rr], off);
            if (ob < best[rr] || (ob == best[rr] && oi < bi[rr])) { best[rr] = ob; bi[rr] = oi; }
        }
    }

    int j = lid & 3;
#pragma unroll
    for (int rr = 0; rr < 4; rr++) {
        const float4* cr = (const float4*)(cb + bi[rr] * CH);
        float4* so = (float4*)(g_state + (size_t)(rbase + 8 * rr) * CH);
        so[2 * j] = __ldg(cr + 2 * j);
        so[2 * j + 1] = __ldg(cr + 2 * j + 1);
    }
}

// ---------- decoder ----------
__global__ __launch_bounds__(256) void dec_kernel(
    const float* __restrict__ wg, const float* __restrict__ bg, float* __restrict__ out)
{
    __shared__ float ws[CH];
    __shared__ float bsh;
    if (threadIdx.x < CH) ws[threadIdx.x] = wg[threadIdx.x];
    if (threadIdx.x == 0) bsh = bg[0];
    __syncthreads();
    int pid = blockIdx.x * 256 + threadIdx.x;
    const float4* sp = (const float4*)(g_state + (size_t)pid * CH);
    float acc = bsh;
#pragma unroll
    for (int q = 0; q < 8; q++) {
        float4 v = __ldg(sp + q);
        acc += v.x * ws[q * 4 + 0] + v.y * ws[q * 4 + 1] + v.z * ws[q * 4 + 2] + v.w * ws[q * 4 + 3];
    }
    out[pid] = sigf(acc);
}

extern "C" void kernel_launch(void* const* d_in, const int* in_sizes, int n_in,
                              void* d_out, int out_size)
{
    const float* x      = (const float*)d_in[0];
    const float* stem_w = (const float*)d_in[1];
    const float* stem_b = (const float*)d_in[2];
    const float* up1_w  = (const float*)d_in[3];
    const float* up1_b  = (const float*)d_in[4];
    const float* up2_w  = (const float*)d_in[5];
    const float* up2_b  = (const float*)d_in[6];
    const float* tau_w  = (const float*)d_in[7];
    const float* tau_b  = (const float*)d_in[8];
    const float* cb     = (const float*)d_in[9];
    const float* dec_w  = (const float*)d_in[10];
    const float* dec_b  = (const float*)d_in[11];

    stem_kernel<<<NPIX / 256, 256>>>(x, stem_w, stem_b);
    for (int t = 0; t < NSTEPS; t++) {
        conv3_relu_kernel<<<NPIX / 256, 128>>>(up1_w, up1_b);
        fused_blend_vq_kernel<<<NPIX / 128, 128>>>(up2_w, up2_b, tau_w, tau_b, cb);
    }
    dec_kernel<<<NPIX / 256, 256>>>(dec_w, dec_b, (float*)d_out);
}